// round 1
// baseline (speedup 1.0000x reference)
#include <cuda_runtime.h>
#include <math.h>

#define BB 64
#define TT 64
#define AA 64
#define HH 1024
#define CC 16

// Scratch (device globals: allowed; no runtime allocation)
__device__ float g_aemb[BB * TT * HH];   // 16 MB
__device__ float g_h[BB * TT * HH];      // 16 MB
__device__ float g_tauc[BB * HH];        // 256 KB: tau_vec @ W2[1024:] + b2

// ---------------------------------------------------------------------------
// Kernel 1: per-batch tau contribution.
// tau_vec(b) is one 1024-vector (identical for all T rows of batch b).
// g_tauc[b,n] = sum_k tau[k] * W2[c][1024+k, n] + b2[c][n]
// grid(HH/256, BB), 256 threads
// ---------------------------------------------------------------------------
__global__ void tau_kernel(const int* __restrict__ timesteps,
                           const int* __restrict__ cat_ids,
                           const float* __restrict__ W2,
                           const float* __restrict__ b2) {
    __shared__ float tau_s[HH];
    const int b   = blockIdx.y;
    const int tid = threadIdx.x;
    const float t = (float)timesteps[b];
    const int half = HH / 2;
    const float scale = logf(10000.0f) / (float)half;
    for (int d = tid; d < HH; d += 256) {
        int j = (d < half) ? d : (d - half);
        float freq = t * expf(-(float)j * scale);
        tau_s[d] = (d < half) ? sinf(freq) : cosf(freq);
    }
    __syncthreads();

    const int c = cat_ids[b];
    const int n = blockIdx.x * 256 + tid;
    // W2[c] is (2H, H) row-major; bottom half starts at row HH
    const float* Wp = W2 + ((size_t)c * 2 * HH * HH) + ((size_t)HH * HH) + n;
    float acc = b2[c * HH + n];
    #pragma unroll 8
    for (int k = 0; k < HH; ++k) {
        acc += tau_s[k] * Wp[(size_t)k * HH];
    }
    g_tauc[b * HH + n] = acc;
}

// ---------------------------------------------------------------------------
// Tiled GEMM: per block computes a 64(M) x 64(N) tile of
//   out[b] = act( A[b] (64 x K) @ W[cat[b]] (K x 1024) + addend )
// ADDMODE 0: addend = bias[c, n]   (C x H tensor)
// ADDMODE 1: addend = vec[b, n]    (B x H tensor, already includes bias)
// ACT 0: identity, ACT 1: swish
// grid(16, BB), 256 threads, Kc = 16, 4x4 per-thread register tile.
// ---------------------------------------------------------------------------
template <int K, int ACT, int ADDMODE>
__global__ void gemm_kernel(const float* __restrict__ Abase,   // (B, 64, K)
                            const float* __restrict__ Wbase,   // (C, K', H), rows [0,K)
                            size_t wstride,                    // elems per category
                            const float* __restrict__ addv,
                            const int* __restrict__ cat_ids,
                            float* __restrict__ out) {         // (B, 64, H)
    __shared__ float As[16][64];      // [k][m]
    __shared__ float Bs[16][64];      // [k][n]

    const int b     = blockIdx.y;
    const int ntile = blockIdx.x;
    const int tid   = threadIdx.x;
    const int c     = cat_ids[b];

    const float* A = Abase + (size_t)b * 64 * K;
    const float* W = Wbase + (size_t)c * wstride + ntile * 64;

    const int tx = tid & 15;   // n-group (0..15)
    const int ty = tid >> 4;   // m-group (0..15)

    float acc[4][4];
    #pragma unroll
    for (int i = 0; i < 4; ++i)
        #pragma unroll
        for (int j = 0; j < 4; ++j) acc[i][j] = 0.0f;

    // Load indices: A tile 64x16 via float4 + transpose store.
    const int a_m  = tid >> 2;        // 0..63
    const int a_kq = tid & 3;         // 0..3 -> k = a_kq*4..+3
    // B tile 16x64 via float4.
    const int b_n4 = tid & 15;        // 0..15 -> n = b_n4*4..+3
    const int b_k  = tid >> 4;        // 0..15

    for (int k0 = 0; k0 < K; k0 += 16) {
        float4 av = *(const float4*)&A[(size_t)a_m * K + k0 + a_kq * 4];
        float4 bv = *(const float4*)&W[(size_t)(k0 + b_k) * HH + b_n4 * 4];
        __syncthreads();
        As[a_kq * 4 + 0][a_m] = av.x;
        As[a_kq * 4 + 1][a_m] = av.y;
        As[a_kq * 4 + 2][a_m] = av.z;
        As[a_kq * 4 + 3][a_m] = av.w;
        *(float4*)&Bs[b_k][b_n4 * 4] = bv;
        __syncthreads();

        #pragma unroll
        for (int k = 0; k < 16; ++k) {
            float4 a4 = *(const float4*)&As[k][ty * 4];
            float4 b4 = *(const float4*)&Bs[k][tx * 4];
            float ar[4] = {a4.x, a4.y, a4.z, a4.w};
            float br[4] = {b4.x, b4.y, b4.z, b4.w};
            #pragma unroll
            for (int i = 0; i < 4; ++i)
                #pragma unroll
                for (int j = 0; j < 4; ++j)
                    acc[i][j] = fmaf(ar[i], br[j], acc[i][j]);
        }
    }

    // Epilogue
    const float* addp = (ADDMODE == 0) ? (addv + (size_t)c * HH)
                                       : (addv + (size_t)b * HH);
    #pragma unroll
    for (int i = 0; i < 4; ++i) {
        const int m = ty * 4 + i;
        float* orow = out + ((size_t)b * TT + m) * HH + ntile * 64;
        #pragma unroll
        for (int j = 0; j < 4; ++j) {
            const int n = tx * 4 + j;
            float v = acc[i][j] + addp[ntile * 64 + n];
            if (ACT == 1) {
                v = v / (1.0f + expf(-v));   // swish: v * sigmoid(v)
            }
            orow[n] = v;
        }
    }
}

extern "C" void kernel_launch(void* const* d_in, const int* in_sizes, int n_in,
                              void* d_out, int out_size) {
    const float* actions   = (const float*)d_in[0];
    const int*   timesteps = (const int*)d_in[1];
    const int*   cat_ids   = (const int*)d_in[2];
    const float* W1 = (const float*)d_in[3];
    const float* b1 = (const float*)d_in[4];
    const float* W2 = (const float*)d_in[5];
    const float* b2 = (const float*)d_in[6];
    const float* W3 = (const float*)d_in[7];
    const float* b3 = (const float*)d_in[8];
    float* out = (float*)d_out;

    float* aemb, * hbuf, * tauc;
    cudaGetSymbolAddress((void**)&aemb, g_aemb);
    cudaGetSymbolAddress((void**)&hbuf, g_h);
    cudaGetSymbolAddress((void**)&tauc, g_tauc);

    // 1) tau contribution (includes b2)
    tau_kernel<<<dim3(HH / 256, BB), 256>>>(timesteps, cat_ids, W2, b2);

    // 2) a_emb = actions @ W1[c] + b1[c]
    gemm_kernel<AA, 0, 0><<<dim3(16, BB), 256>>>(
        actions, W1, (size_t)AA * HH, b1, cat_ids, aemb);

    // 3) h = swish(a_emb @ W2[c][:1024] + tauc[b])
    gemm_kernel<HH, 1, 1><<<dim3(16, BB), 256>>>(
        aemb, W2, (size_t)2 * HH * HH, tauc, cat_ids, hbuf);

    // 4) out = h @ W3[c] + b3[c]
    gemm_kernel<HH, 0, 0><<<dim3(16, BB), 256>>>(
        hbuf, W3, (size_t)HH * HH, b3, cat_ids, out);
}

// round 4
// speedup vs baseline: 1.6528x; 1.6528x over previous
#include <cuda_runtime.h>
#include <cuda_bf16.h>
#include <math.h>
#include <stdint.h>

#define BB 64
#define TT 64
#define AA 64
#define HH 1024
#define CC 16

#define NT 128     // N cols per CTA
#define KC 32      // K floats per chunk

// Scratch (device globals; no runtime allocation)
__device__ float g_aemb[BB * TT * HH];
__device__ float g_h[BB * TT * HH];
__device__ float g_tauc[BB * HH];
__device__ float g_tau[BB * HH];
__device__ int   g_cat_cnt[CC];
__device__ int   g_cat_list[CC * BB];

// ---------------- helpers ----------------
__device__ __forceinline__ void split_pair(float x, float y, uint32_t& h, uint32_t& l) {
    __nv_bfloat162 hb = __floats2bfloat162_rn(x, y);          // .x = x(low), .y = y(high)
    float hx = __bfloat162float(hb.x);
    float hy = __bfloat162float(hb.y);
    __nv_bfloat162 lb = __floats2bfloat162_rn(x - hx, y - hy);
    h = *reinterpret_cast<uint32_t*>(&hb);
    l = *reinterpret_cast<uint32_t*>(&lb);
}

__device__ __forceinline__ void mma_bf16(float* c, const uint32_t* a, uint32_t b0, uint32_t b1) {
    asm volatile(
        "mma.sync.aligned.m16n8k16.row.col.f32.bf16.bf16.f32 "
        "{%0,%1,%2,%3}, {%4,%5,%6,%7}, {%8,%9}, {%0,%1,%2,%3};"
        : "+f"(c[0]), "+f"(c[1]), "+f"(c[2]), "+f"(c[3])
        : "r"(a[0]), "r"(a[1]), "r"(a[2]), "r"(a[3]), "r"(b0), "r"(b1));
}

// ---------------------------------------------------------------------------
// prep: bucket batches by category (deterministic: per-cat sequential scan)
// ---------------------------------------------------------------------------
__global__ void prep_kernel(const int* __restrict__ cat_ids) {
    int c = threadIdx.x;
    if (c >= CC) return;
    int cnt = 0;
    for (int b = 0; b < BB; ++b)
        if (cat_ids[b] == c) g_cat_list[c * BB + cnt++] = b;
    g_cat_cnt[c] = cnt;
}

// ---------------------------------------------------------------------------
// tau1: per-batch sinusoidal embedding vector (1024)
// ---------------------------------------------------------------------------
__global__ void tau1_kernel(const int* __restrict__ timesteps) {
    const int b = blockIdx.x;
    const int tid = threadIdx.x;
    const float t = (float)timesteps[b];
    const int half = HH / 2;
    const float scale = logf(10000.0f) / (float)half;
    for (int d = tid; d < HH; d += 256) {
        int j = (d < half) ? d : (d - half);
        float f = t * expf(-(float)j * scale);
        g_tau[b * HH + d] = (d < half) ? sinf(f) : cosf(f);
    }
}

// ---------------------------------------------------------------------------
// tau2: cat-grouped matvec. g_tauc[b,n] = tau_b . W2[c][1024:, n] + b2[c][n]
// grid(HH/128, CC), 128 threads. Each weight column read once per category.
// ---------------------------------------------------------------------------
__global__ void tau2_kernel(const float* __restrict__ W2,
                            const float* __restrict__ b2) {
    const int cat = blockIdx.y;
    const int n   = blockIdx.x * 128 + threadIdx.x;
    const int cnt = g_cat_cnt[cat];
    if (cnt == 0) return;

    __shared__ float ts[8 * HH];
    const float* Wp = W2 + (size_t)cat * 2 * HH * HH + (size_t)HH * HH + n;
    const float bias = b2[cat * HH + n];

    for (int base = 0; base < cnt; base += 8) {
        int nb = min(8, cnt - base);
        __syncthreads();
        for (int bl = 0; bl < nb; ++bl) {
            int bb = g_cat_list[cat * BB + base + bl];
            for (int d = threadIdx.x; d < HH; d += 128)
                ts[bl * HH + d] = g_tau[bb * HH + d];
        }
        __syncthreads();
        float acc[8] = {0, 0, 0, 0, 0, 0, 0, 0};
        #pragma unroll 4
        for (int k = 0; k < HH; ++k) {
            float w = Wp[(size_t)k * HH];
            #pragma unroll
            for (int bl = 0; bl < 8; ++bl)
                acc[bl] = fmaf(ts[bl * HH + k], w, acc[bl]);
        }
        for (int bl = 0; bl < nb; ++bl) {
            int bb = g_cat_list[cat * BB + base + bl];
            g_tauc[bb * HH + n] = acc[bl] + bias;
        }
    }
}

// ---------------------------------------------------------------------------
// Split-bf16 mma.sync GEMM layer:
//   out[b] = act( A[b](64 x K) @ W[cat[b]](K x 1024) + addend )
// grid(HH/NT, BB), 256 threads (8 warps: 2 m-warps x 4 n-warps, 32x32 each).
// ADDMODE 0: addend = bias[c,:]; 1: addend = vec[b,:]. ACT 1: swish.
// ---------------------------------------------------------------------------
template <int K, int ACT, int ADDMODE>
__global__ void __launch_bounds__(256, 2)
mma_layer(const float* __restrict__ Abase,
          const float* __restrict__ Wbase,
          size_t wcat_stride,
          const float* __restrict__ addv,
          const int* __restrict__ cat_ids,
          float* __restrict__ out) {
    // A: k-pair packed [m=64][kp=16], stride 20 words (bank-clean frag reads)
    __shared__ __align__(16) uint32_t As_hi[64 * 20];
    __shared__ __align__(16) uint32_t As_lo[64 * 20];
    // B: k-pair packed [kp=16][n=128], stride 136 words
    __shared__ __align__(16) uint32_t Bs_hi[16 * 136];
    __shared__ __align__(16) uint32_t Bs_lo[16 * 136];

    const int tid  = threadIdx.x;
    const int lane = tid & 31;
    const int warp = tid >> 5;
    const int wm   = warp >> 2;   // 0..1
    const int wn   = warp & 3;    // 0..3
    const int b    = blockIdx.y;
    const int nt   = blockIdx.x;
    const int c    = cat_ids[b];

    const float* A = Abase + (size_t)b * 64 * K;
    const float* W = Wbase + (size_t)c * wcat_stride + nt * NT;

    float acc[2][4][4];
    #pragma unroll
    for (int i = 0; i < 2; ++i)
        #pragma unroll
        for (int j = 0; j < 4; ++j)
            #pragma unroll
            for (int q = 0; q < 4; ++q) acc[i][j][q] = 0.0f;

    constexpr int NCHUNK = K / KC;

    // Load mappings:
    // A: item i = tid + 256*r : kq = i&7 (float4 along k), m = i>>3
    // B: item i = tid + 256*r : nq = i&31 (float4 along n), kp = i>>5 (k pair)
    float4 pa[2], pb0[2], pb1[2];
    {
        #pragma unroll
        for (int r = 0; r < 2; ++r) {
            int i = tid + r * 256, kq = i & 7, m = i >> 3;
            pa[r] = *(const float4*)&A[(size_t)m * K + kq * 4];
        }
        #pragma unroll
        for (int r = 0; r < 2; ++r) {
            int i = tid + r * 256, nq = i & 31, kp = i >> 5;
            pb0[r] = *(const float4*)&W[(size_t)(kp * 2)     * HH + nq * 4];
            pb1[r] = *(const float4*)&W[(size_t)(kp * 2 + 1) * HH + nq * 4];
        }
    }

    for (int ch = 0; ch < NCHUNK; ++ch) {
        __syncthreads();   // previous iteration's frag reads complete

        // ---- STS (convert fp32 -> bf16 hi/lo, k-pair packed) ----
        #pragma unroll
        for (int r = 0; r < 2; ++r) {
            int i = tid + r * 256, kq = i & 7, m = i >> 3;
            float4 v = pa[r];
            uint32_t h0, l0, h1, l1;
            split_pair(v.x, v.y, h0, l0);
            split_pair(v.z, v.w, h1, l1);
            int idx = m * 20 + kq * 2;
            *(uint2*)&As_hi[idx] = make_uint2(h0, h1);
            *(uint2*)&As_lo[idx] = make_uint2(l0, l1);
        }
        #pragma unroll
        for (int r = 0; r < 2; ++r) {
            int i = tid + r * 256, nq = i & 31, kp = i >> 5;
            float4 v0 = pb0[r], v1 = pb1[r];
            uint32_t h[4], l[4];
            split_pair(v0.x, v1.x, h[0], l[0]);
            split_pair(v0.y, v1.y, h[1], l[1]);
            split_pair(v0.z, v1.z, h[2], l[2]);
            split_pair(v0.w, v1.w, h[3], l[3]);
            int idx = kp * 136 + nq * 4;
            *(uint4*)&Bs_hi[idx] = make_uint4(h[0], h[1], h[2], h[3]);
            *(uint4*)&Bs_lo[idx] = make_uint4(l[0], l[1], l[2], l[3]);
        }
        __syncthreads();

        // ---- prefetch next chunk (overlaps MMA below) ----
        if (ch + 1 < NCHUNK) {
            int k0 = (ch + 1) * KC;
            #pragma unroll
            for (int r = 0; r < 2; ++r) {
                int i = tid + r * 256, kq = i & 7, m = i >> 3;
                pa[r] = *(const float4*)&A[(size_t)m * K + k0 + kq * 4];
            }
            #pragma unroll
            for (int r = 0; r < 2; ++r) {
                int i = tid + r * 256, nq = i & 31, kp = i >> 5;
                pb0[r] = *(const float4*)&W[(size_t)(k0 + kp * 2)     * HH + nq * 4];
                pb1[r] = *(const float4*)&W[(size_t)(k0 + kp * 2 + 1) * HH + nq * 4];
            }
        }

        // ---- MMA phase: two k16 steps ----
        const int lr = lane >> 2;   // 0..7
        const int lc = lane & 3;    // 0..3
        #pragma unroll
        for (int t = 0; t < 2; ++t) {
            uint32_t ah[2][4], al[2][4];
            #pragma unroll
            for (int ms = 0; ms < 2; ++ms) {
                int r0 = wm * 32 + ms * 16 + lr;
                int base0 = r0 * 20 + t * 8 + lc;
                int base1 = (r0 + 8) * 20 + t * 8 + lc;
                ah[ms][0] = As_hi[base0];
                ah[ms][1] = As_hi[base1];
                ah[ms][2] = As_hi[base0 + 4];
                ah[ms][3] = As_hi[base1 + 4];
                al[ms][0] = As_lo[base0];
                al[ms][1] = As_lo[base1];
                al[ms][2] = As_lo[base0 + 4];
                al[ms][3] = As_lo[base1 + 4];
            }
            #pragma unroll
            for (int nf = 0; nf < 4; ++nf) {
                int n0 = wn * 32 + nf * 8 + lr;
                int kb = (t * 8 + lc) * 136 + n0;
                uint32_t bh0 = Bs_hi[kb];
                uint32_t bh1 = Bs_hi[kb + 4 * 136];
                uint32_t bl0 = Bs_lo[kb];
                uint32_t bl1 = Bs_lo[kb + 4 * 136];
                #pragma unroll
                for (int ms = 0; ms < 2; ++ms) {
                    mma_bf16(acc[ms][nf], ah[ms], bh0, bh1);   // hi*hi
                    mma_bf16(acc[ms][nf], ah[ms], bl0, bl1);   // hi*lo
                    mma_bf16(acc[ms][nf], al[ms], bh0, bh1);   // lo*hi
                }
            }
        }
    }

    // ---- epilogue ----
    const float* addp = (ADDMODE == 0) ? (addv + (size_t)c * HH)
                                       : (addv + (size_t)b * HH);
    const int lr = lane >> 2;
    const int lc = lane & 3;
    #pragma unroll
    for (int ms = 0; ms < 2; ++ms) {
        int r0 = wm * 32 + ms * 16 + lr;
        #pragma unroll
        for (int nf = 0; nf < 4; ++nf) {
            int ncol = nt * NT + wn * 32 + nf * 8 + lc * 2;
            float bv0 = addp[ncol], bv1 = addp[ncol + 1];
            float v0 = acc[ms][nf][0] + bv0;
            float v1 = acc[ms][nf][1] + bv1;
            float v2 = acc[ms][nf][2] + bv0;
            float v3 = acc[ms][nf][3] + bv1;
            if (ACT == 1) {
                v0 = v0 / (1.0f + expf(-v0));
                v1 = v1 / (1.0f + expf(-v1));
                v2 = v2 / (1.0f + expf(-v2));
                v3 = v3 / (1.0f + expf(-v3));
            }
            *(float2*)&out[((size_t)b * TT + r0)     * HH + ncol] = make_float2(v0, v1);
            *(float2*)&out[((size_t)b * TT + r0 + 8) * HH + ncol] = make_float2(v2, v3);
        }
    }
}

extern "C" void kernel_launch(void* const* d_in, const int* in_sizes, int n_in,
                              void* d_out, int out_size) {
    const float* actions   = (const float*)d_in[0];
    const int*   timesteps = (const int*)d_in[1];
    const int*   cat_ids   = (const int*)d_in[2];
    const float* W1 = (const float*)d_in[3];
    const float* b1 = (const float*)d_in[4];
    const float* W2 = (const float*)d_in[5];
    const float* b2 = (const float*)d_in[6];
    const float* W3 = (const float*)d_in[7];
    const float* b3 = (const float*)d_in[8];
    float* out = (float*)d_out;

    float* aemb, * hbuf, * tauc;
    cudaGetSymbolAddress((void**)&aemb, g_aemb);
    cudaGetSymbolAddress((void**)&hbuf, g_h);
    cudaGetSymbolAddress((void**)&tauc, g_tauc);

    // tau pipeline (cat-grouped to cut weight traffic 4x)
    prep_kernel<<<1, CC>>>(cat_ids);
    tau1_kernel<<<BB, 256>>>(timesteps);
    // layer 1 (small) before tau2 so tau2/L1 DRAM traffic interleaves a bit
    mma_layer<AA, 0, 0><<<dim3(HH / NT, BB), 256>>>(
        actions, W1, (size_t)AA * HH, b1, cat_ids, aemb);
    tau2_kernel<<<dim3(HH / 128, CC), 128>>>(W2, b2);

    // layer 2: h = swish(a_emb @ W2[:1024] + tauc)
    mma_layer<HH, 1, 1><<<dim3(HH / NT, BB), 256>>>(
        aemb, W2, (size_t)2 * HH * HH, tauc, cat_ids, hbuf);

    // layer 3
    mma_layer<HH, 0, 0><<<dim3(HH / NT, BB), 256>>>(
        hbuf, W3, (size_t)HH * HH, b3, cat_ids, out);
}

// round 7
// speedup vs baseline: 2.6060x; 1.5767x over previous
#include <cuda_runtime.h>
#include <cuda_bf16.h>
#include <math.h>
#include <stdint.h>

#define BB 64
#define TT 64
#define AA 64
#define HH 1024
#define CC 16

#define NT 128     // N cols per CTA
#define KC 32      // K floats per chunk

#define KSPLIT 8
#define TAU_KB (HH / KSPLIT)   // 128

// Scratch (device globals; no runtime allocation)
__device__ float g_aemb[BB * TT * HH];
__device__ float g_h[BB * TT * HH];
__device__ float g_tauc[BB * HH];
__device__ float g_tau[BB * HH];
__device__ float g_part[KSPLIT * BB * HH];   // 2 MB partials
__device__ int   g_cat_cnt[CC];
__device__ int   g_cat_list[CC * BB];

// ---------------- helpers ----------------
__device__ __forceinline__ void split_pair(float x, float y, uint32_t& h, uint32_t& l) {
    __nv_bfloat162 hb = __floats2bfloat162_rn(x, y);
    float hx = __bfloat162float(hb.x);
    float hy = __bfloat162float(hb.y);
    __nv_bfloat162 lb = __floats2bfloat162_rn(x - hx, y - hy);
    h = *reinterpret_cast<uint32_t*>(&hb);
    l = *reinterpret_cast<uint32_t*>(&lb);
}

__device__ __forceinline__ void mma_bf16(float* c, const uint32_t* a, uint32_t b0, uint32_t b1) {
    asm volatile(
        "mma.sync.aligned.m16n8k16.row.col.f32.bf16.bf16.f32 "
        "{%0,%1,%2,%3}, {%4,%5,%6,%7}, {%8,%9}, {%0,%1,%2,%3};"
        : "+f"(c[0]), "+f"(c[1]), "+f"(c[2]), "+f"(c[3])
        : "r"(a[0]), "r"(a[1]), "r"(a[2]), "r"(a[3]), "r"(b0), "r"(b1));
}

// ---------------------------------------------------------------------------
// prep: bucket batches by category (deterministic sequential scan)
// ---------------------------------------------------------------------------
__global__ void prep_kernel(const int* __restrict__ cat_ids) {
    int c = threadIdx.x;
    if (c >= CC) return;
    int cnt = 0;
    for (int b = 0; b < BB; ++b)
        if (cat_ids[b] == c) g_cat_list[c * BB + cnt++] = b;
    g_cat_cnt[c] = cnt;
}

// ---------------------------------------------------------------------------
// tau1: per-batch sinusoidal embedding vector (1024)
// ---------------------------------------------------------------------------
__global__ void tau1_kernel(const int* __restrict__ timesteps) {
    const int b = blockIdx.x;
    const int tid = threadIdx.x;
    const float t = (float)timesteps[b];
    const int half = HH / 2;
    const float scale = logf(10000.0f) / (float)half;
    for (int d = tid; d < HH; d += 256) {
        int j = (d < half) ? d : (d - half);
        float f = t * expf(-(float)j * scale);
        g_tau[b * HH + d] = (d < half) ? sinf(f) : cosf(f);
    }
}

// ---------------------------------------------------------------------------
// tau2: cat-grouped, K-split matvec partials.
// g_part[z][b][n] = sum_{k in slice z} tau_b[k] * W2[c][1024+k, n]
// grid(HH/2/128, CC, KSPLIT), 128 threads, float2 loads.
// ---------------------------------------------------------------------------
__global__ void tau2_kernel(const float* __restrict__ W2) {
    const int cat = blockIdx.y;
    const int z   = blockIdx.z;
    const int tid = threadIdx.x;                 // 0..127
    const int n2  = blockIdx.x * 128 + tid;      // float2 column index
    const int cnt = g_cat_cnt[cat];
    if (cnt == 0) return;

    __shared__ float ts[8][TAU_KB];
    const int k0 = z * TAU_KB;
    const float* Wp = W2 + (size_t)cat * 2 * HH * HH
                         + (size_t)(HH + k0) * HH + 2 * n2;

    for (int base = 0; base < cnt; base += 8) {
        int nb = min(8, cnt - base);
        __syncthreads();
        for (int bl = 0; bl < nb; ++bl) {
            int bb = g_cat_list[cat * BB + base + bl];
            ts[bl][tid] = g_tau[bb * HH + k0 + tid];
        }
        __syncthreads();
        float2 acc[8];
        #pragma unroll
        for (int bl = 0; bl < 8; ++bl) acc[bl] = make_float2(0.f, 0.f);
        #pragma unroll 4
        for (int k = 0; k < TAU_KB; ++k) {
            float2 w = *(const float2*)&Wp[(size_t)k * HH];
            #pragma unroll
            for (int bl = 0; bl < 8; ++bl) {
                acc[bl].x = fmaf(ts[bl][k], w.x, acc[bl].x);
                acc[bl].y = fmaf(ts[bl][k], w.y, acc[bl].y);
            }
        }
        for (int bl = 0; bl < nb; ++bl) {
            int bb = g_cat_list[cat * BB + base + bl];
            *(float2*)&g_part[((size_t)z * BB + bb) * HH + 2 * n2] = acc[bl];
        }
    }
}

// ---------------------------------------------------------------------------
// tau3: deterministic reduce of partials + bias -> g_tauc
// grid(HH/256, BB), 256 threads
// ---------------------------------------------------------------------------
__global__ void tau3_kernel(const int* __restrict__ cat_ids,
                            const float* __restrict__ b2) {
    const int b = blockIdx.y;
    const int n = blockIdx.x * 256 + threadIdx.x;
    const int c = cat_ids[b];
    float s = b2[c * HH + n];
    #pragma unroll
    for (int z = 0; z < KSPLIT; ++z)
        s += g_part[((size_t)z * BB + b) * HH + n];
    g_tauc[b * HH + n] = s;
}

// ---------------------------------------------------------------------------
// Split-bf16 mma.sync GEMM layer:
//   out[b] = act( A[b](64 x K) @ W[cat[b]](K x 1024) + addend )
// grid(HH/NT, BB), 256 threads (8 warps: 2 m-warps x 4 n-warps, 32x32 each).
// ---------------------------------------------------------------------------
template <int K, int ACT, int ADDMODE>
__global__ void __launch_bounds__(256, 2)
mma_layer(const float* __restrict__ Abase,
          const float* __restrict__ Wbase,
          size_t wcat_stride,
          const float* __restrict__ addv,
          const int* __restrict__ cat_ids,
          float* __restrict__ out) {
    __shared__ __align__(16) uint32_t As_hi[64 * 20];
    __shared__ __align__(16) uint32_t As_lo[64 * 20];
    __shared__ __align__(16) uint32_t Bs_hi[16 * 136];
    __shared__ __align__(16) uint32_t Bs_lo[16 * 136];

    const int tid  = threadIdx.x;
    const int lane = tid & 31;
    const int warp = tid >> 5;
    const int wm   = warp >> 2;
    const int wn   = warp & 3;
    const int b    = blockIdx.y;
    const int nt   = blockIdx.x;
    const int c    = cat_ids[b];

    const float* A = Abase + (size_t)b * 64 * K;
    const float* W = Wbase + (size_t)c * wcat_stride + nt * NT;

    float acc[2][4][4];
    #pragma unroll
    for (int i = 0; i < 2; ++i)
        #pragma unroll
        for (int j = 0; j < 4; ++j)
            #pragma unroll
            for (int q = 0; q < 4; ++q) acc[i][j][q] = 0.0f;

    constexpr int NCHUNK = K / KC;

    float4 pa[2], pb0[2], pb1[2];
    {
        #pragma unroll
        for (int r = 0; r < 2; ++r) {
            int i = tid + r * 256, kq = i & 7, m = i >> 3;
            pa[r] = *(const float4*)&A[(size_t)m * K + kq * 4];
        }
        #pragma unroll
        for (int r = 0; r < 2; ++r) {
            int i = tid + r * 256, nq = i & 31, kp = i >> 5;
            pb0[r] = *(const float4*)&W[(size_t)(kp * 2)     * HH + nq * 4];
            pb1[r] = *(const float4*)&W[(size_t)(kp * 2 + 1) * HH + nq * 4];
        }
    }

    for (int ch = 0; ch < NCHUNK; ++ch) {
        __syncthreads();

        #pragma unroll
        for (int r = 0; r < 2; ++r) {
            int i = tid + r * 256, kq = i & 7, m = i >> 3;
            float4 v = pa[r];
            uint32_t h0, l0, h1, l1;
            split_pair(v.x, v.y, h0, l0);
            split_pair(v.z, v.w, h1, l1);
            int idx = m * 20 + kq * 2;
            *(uint2*)&As_hi[idx] = make_uint2(h0, h1);
            *(uint2*)&As_lo[idx] = make_uint2(l0, l1);
        }
        #pragma unroll
        for (int r = 0; r < 2; ++r) {
            int i = tid + r * 256, nq = i & 31, kp = i >> 5;
            float4 v0 = pb0[r], v1 = pb1[r];
            uint32_t h[4], l[4];
            split_pair(v0.x, v1.x, h[0], l[0]);
            split_pair(v0.y, v1.y, h[1], l[1]);
            split_pair(v0.z, v1.z, h[2], l[2]);
            split_pair(v0.w, v1.w, h[3], l[3]);
            int idx = kp * 136 + nq * 4;
            *(uint4*)&Bs_hi[idx] = make_uint4(h[0], h[1], h[2], h[3]);
            *(uint4*)&Bs_lo[idx] = make_uint4(l[0], l[1], l[2], l[3]);
        }
        __syncthreads();

        if (ch + 1 < NCHUNK) {
            int k0 = (ch + 1) * KC;
            #pragma unroll
            for (int r = 0; r < 2; ++r) {
                int i = tid + r * 256, kq = i & 7, m = i >> 3;
                pa[r] = *(const float4*)&A[(size_t)m * K + k0 + kq * 4];
            }
            #pragma unroll
            for (int r = 0; r < 2; ++r) {
                int i = tid + r * 256, nq = i & 31, kp = i >> 5;
                pb0[r] = *(const float4*)&W[(size_t)(k0 + kp * 2)     * HH + nq * 4];
                pb1[r] = *(const float4*)&W[(size_t)(k0 + kp * 2 + 1) * HH + nq * 4];
            }
        }

        const int lr = lane >> 2;
        const int lc = lane & 3;
        #pragma unroll
        for (int t = 0; t < 2; ++t) {
            uint32_t ah[2][4], al[2][4];
            #pragma unroll
            for (int ms = 0; ms < 2; ++ms) {
                int r0 = wm * 32 + ms * 16 + lr;
                int base0 = r0 * 20 + t * 8 + lc;
                int base1 = (r0 + 8) * 20 + t * 8 + lc;
                ah[ms][0] = As_hi[base0];
                ah[ms][1] = As_hi[base1];
                ah[ms][2] = As_hi[base0 + 4];
                ah[ms][3] = As_hi[base1 + 4];
                al[ms][0] = As_lo[base0];
                al[ms][1] = As_lo[base1];
                al[ms][2] = As_lo[base0 + 4];
                al[ms][3] = As_lo[base1 + 4];
            }
            #pragma unroll
            for (int nf = 0; nf < 4; ++nf) {
                int n0 = wn * 32 + nf * 8 + lr;
                int kb = (t * 8 + lc) * 136 + n0;
                uint32_t bh0 = Bs_hi[kb];
                uint32_t bh1 = Bs_hi[kb + 4 * 136];
                uint32_t bl0 = Bs_lo[kb];
                uint32_t bl1 = Bs_lo[kb + 4 * 136];
                #pragma unroll
                for (int ms = 0; ms < 2; ++ms) {
                    mma_bf16(acc[ms][nf], ah[ms], bh0, bh1);
                    mma_bf16(acc[ms][nf], ah[ms], bl0, bl1);
                    mma_bf16(acc[ms][nf], al[ms], bh0, bh1);
                }
            }
        }
    }

    const float* addp = (ADDMODE == 0) ? (addv + (size_t)c * HH)
                                       : (addv + (size_t)b * HH);
    const int lr = lane >> 2;
    const int lc = lane & 3;
    #pragma unroll
    for (int ms = 0; ms < 2; ++ms) {
        int r0 = wm * 32 + ms * 16 + lr;
        #pragma unroll
        for (int nf = 0; nf < 4; ++nf) {
            int ncol = nt * NT + wn * 32 + nf * 8 + lc * 2;
            float bv0 = addp[ncol], bv1 = addp[ncol + 1];
            float v0 = acc[ms][nf][0] + bv0;
            float v1 = acc[ms][nf][1] + bv1;
            float v2 = acc[ms][nf][2] + bv0;
            float v3 = acc[ms][nf][3] + bv1;
            if (ACT == 1) {
                v0 = v0 / (1.0f + expf(-v0));
                v1 = v1 / (1.0f + expf(-v1));
                v2 = v2 / (1.0f + expf(-v2));
                v3 = v3 / (1.0f + expf(-v3));
            }
            *(float2*)&out[((size_t)b * TT + r0)     * HH + ncol] = make_float2(v0, v1);
            *(float2*)&out[((size_t)b * TT + r0 + 8) * HH + ncol] = make_float2(v2, v3);
        }
    }
}

extern "C" void kernel_launch(void* const* d_in, const int* in_sizes, int n_in,
                              void* d_out, int out_size) {
    const float* actions   = (const float*)d_in[0];
    const int*   timesteps = (const int*)d_in[1];
    const int*   cat_ids   = (const int*)d_in[2];
    const float* W1 = (const float*)d_in[3];
    const float* b1 = (const float*)d_in[4];
    const float* W2 = (const float*)d_in[5];
    const float* b2 = (const float*)d_in[6];
    const float* W3 = (const float*)d_in[7];
    const float* b3 = (const float*)d_in[8];
    float* out = (float*)d_out;

    float* aemb, * hbuf, * tauc;
    cudaGetSymbolAddress((void**)&aemb, g_aemb);
    cudaGetSymbolAddress((void**)&hbuf, g_h);
    cudaGetSymbolAddress((void**)&tauc, g_tauc);

    prep_kernel<<<1, CC>>>(cat_ids);
    tau1_kernel<<<BB, 256>>>(timesteps);

    // layer 1 (small GEMM)
    mma_layer<AA, 0, 0><<<dim3(HH / NT, BB), 256>>>(
        actions, W1, (size_t)AA * HH, b1, cat_ids, aemb);

    // tau matvec: K-split partials + deterministic reduce
    tau2_kernel<<<dim3(HH / 2 / 128, CC, KSPLIT), 128>>>(W2);
    tau3_kernel<<<dim3(HH / 256, BB), 256>>>(cat_ids, b2);

    // layer 2: h = swish(a_emb @ W2[:1024] + tauc)
    mma_layer<HH, 1, 1><<<dim3(HH / NT, BB), 256>>>(
        aemb, W2, (size_t)2 * HH * HH, tauc, cat_ids, hbuf);

    // layer 3
    mma_layer<HH, 0, 0><<<dim3(HH / NT, BB), 256>>>(
        hbuf, W3, (size_t)HH * HH, b3, cat_ids, out);
}

// round 8
// speedup vs baseline: 2.8245x; 1.0839x over previous
#include <cuda_runtime.h>
#include <cuda_bf16.h>
#include <math.h>
#include <stdint.h>

#define BB 64
#define TT 64
#define AA 64
#define HH 1024
#define CC 16

#define NT 128     // N cols per CTA
#define KC 32      // K floats per chunk

#define KSPLIT 16
#define TAU_KB (HH / KSPLIT)   // 64

// Scratch (device globals; no runtime allocation)
__device__ float g_aemb[BB * TT * HH];
__device__ float g_h[BB * TT * HH];
__device__ float g_tauc[BB * HH];
__device__ float g_tau[BB * HH];
__device__ float g_part[KSPLIT * BB * HH];   // 4 MB partials
__device__ int   g_cat_cnt[CC];
__device__ int   g_cat_list[CC * BB];

// ---------------- helpers ----------------
__device__ __forceinline__ uint32_t smem_u32(const void* p) {
    uint32_t a;
    asm("{ .reg .u64 t; cvta.to.shared.u64 t, %1; cvt.u32.u64 %0, t; }"
        : "=r"(a) : "l"(p));
    return a;
}
__device__ __forceinline__ void split_pair(float x, float y, uint32_t& h, uint32_t& l) {
    __nv_bfloat162 hb = __floats2bfloat162_rn(x, y);   // low 16 bits = x
    float hx = __bfloat162float(hb.x);
    float hy = __bfloat162float(hb.y);
    __nv_bfloat162 lb = __floats2bfloat162_rn(x - hx, y - hy);
    h = *reinterpret_cast<uint32_t*>(&hb);
    l = *reinterpret_cast<uint32_t*>(&lb);
}
__device__ __forceinline__ void mma_bf16(float* c, const uint32_t* a, uint32_t b0, uint32_t b1) {
    asm volatile(
        "mma.sync.aligned.m16n8k16.row.col.f32.bf16.bf16.f32 "
        "{%0,%1,%2,%3}, {%4,%5,%6,%7}, {%8,%9}, {%0,%1,%2,%3};"
        : "+f"(c[0]), "+f"(c[1]), "+f"(c[2]), "+f"(c[3])
        : "r"(a[0]), "r"(a[1]), "r"(a[2]), "r"(a[3]), "r"(b0), "r"(b1));
}
__device__ __forceinline__ void ldsm_x4(uint32_t* r, uint32_t addr) {
    asm volatile("ldmatrix.sync.aligned.m8n8.x4.shared.b16 {%0,%1,%2,%3}, [%4];"
                 : "=r"(r[0]), "=r"(r[1]), "=r"(r[2]), "=r"(r[3]) : "r"(addr));
}
__device__ __forceinline__ void ldsm_x4_t(uint32_t* r, uint32_t addr) {
    asm volatile("ldmatrix.sync.aligned.m8n8.x4.trans.shared.b16 {%0,%1,%2,%3}, [%4];"
                 : "=r"(r[0]), "=r"(r[1]), "=r"(r[2]), "=r"(r[3]) : "r"(addr));
}

// ---------------------------------------------------------------------------
// prep: bucket batches by category (deterministic sequential scan)
// ---------------------------------------------------------------------------
__global__ void prep_kernel(const int* __restrict__ cat_ids) {
    int c = threadIdx.x;
    if (c >= CC) return;
    int cnt = 0;
    for (int b = 0; b < BB; ++b)
        if (cat_ids[b] == c) g_cat_list[c * BB + cnt++] = b;
    g_cat_cnt[c] = cnt;
}

// ---------------------------------------------------------------------------
// tau1: per-batch sinusoidal embedding vector (1024)
// ---------------------------------------------------------------------------
__global__ void tau1_kernel(const int* __restrict__ timesteps) {
    const int b = blockIdx.x;
    const int tid = threadIdx.x;
    const float t = (float)timesteps[b];
    const int half = HH / 2;
    const float scale = logf(10000.0f) / (float)half;
    for (int d = tid; d < HH; d += 256) {
        int j = (d < half) ? d : (d - half);
        float f = t * expf(-(float)j * scale);
        g_tau[b * HH + d] = (d < half) ? sinf(f) : cosf(f);
    }
}

// ---------------------------------------------------------------------------
// tau2: cat-grouped, K-split matvec partials.
// grid(HH/2/128, CC, KSPLIT), 128 threads, float2 loads.
// ---------------------------------------------------------------------------
__global__ void tau2_kernel(const float* __restrict__ W2) {
    const int cat = blockIdx.y;
    const int z   = blockIdx.z;
    const int tid = threadIdx.x;
    const int n2  = blockIdx.x * 128 + tid;
    const int cnt = g_cat_cnt[cat];
    if (cnt == 0) return;

    __shared__ float ts[8][TAU_KB];
    const int k0 = z * TAU_KB;
    const float* Wp = W2 + (size_t)cat * 2 * HH * HH
                         + (size_t)(HH + k0) * HH + 2 * n2;

    for (int base = 0; base < cnt; base += 8) {
        int nb = min(8, cnt - base);
        __syncthreads();
        for (int bl = 0; bl < nb; ++bl) {
            int bb = g_cat_list[cat * BB + base + bl];
            for (int d = tid; d < TAU_KB; d += 128)
                ts[bl][d] = g_tau[bb * HH + k0 + d];
        }
        __syncthreads();
        float2 acc[8];
        #pragma unroll
        for (int bl = 0; bl < 8; ++bl) acc[bl] = make_float2(0.f, 0.f);
        #pragma unroll 4
        for (int k = 0; k < TAU_KB; ++k) {
            float2 w = *(const float2*)&Wp[(size_t)k * HH];
            #pragma unroll
            for (int bl = 0; bl < 8; ++bl) {
                acc[bl].x = fmaf(ts[bl][k], w.x, acc[bl].x);
                acc[bl].y = fmaf(ts[bl][k], w.y, acc[bl].y);
            }
        }
        for (int bl = 0; bl < nb; ++bl) {
            int bb = g_cat_list[cat * BB + base + bl];
            *(float2*)&g_part[((size_t)z * BB + bb) * HH + 2 * n2] = acc[bl];
        }
    }
}

// ---------------------------------------------------------------------------
// tau3: deterministic reduce of partials + bias -> g_tauc
// ---------------------------------------------------------------------------
__global__ void tau3_kernel(const int* __restrict__ cat_ids,
                            const float* __restrict__ b2) {
    const int b = blockIdx.y;
    const int n = blockIdx.x * 256 + threadIdx.x;
    const int c = cat_ids[b];
    float s = b2[c * HH + n];
    #pragma unroll
    for (int z = 0; z < KSPLIT; ++z)
        s += g_part[((size_t)z * BB + b) * HH + n];
    g_tauc[b * HH + n] = s;
}

// ---------------------------------------------------------------------------
// Split-bf16 mma.sync GEMM layer with ldmatrix fragment loads.
//   out[b] = act( A[b](64 x K) @ W[cat[b]](K x 1024) + addend )
// grid(HH/NT, BB), 256 threads (8 warps: 2 m-warps x 4 n-warps, 32x32 each).
// A smem: bf16 [m=64][k=32], row stride 80 B (20 words).
// B smem: bf16 [k=32][n=128], row stride 272 B (68 words).
// ---------------------------------------------------------------------------
template <int K, int ACT, int ADDMODE>
__global__ void __launch_bounds__(256, 2)
mma_layer(const float* __restrict__ Abase,
          const float* __restrict__ Wbase,
          size_t wcat_stride,
          const float* __restrict__ addv,
          const int* __restrict__ cat_ids,
          float* __restrict__ out) {
    __shared__ __align__(16) uint32_t As_hi[64 * 20];
    __shared__ __align__(16) uint32_t As_lo[64 * 20];
    __shared__ __align__(16) uint32_t Bs_hi[32 * 68];
    __shared__ __align__(16) uint32_t Bs_lo[32 * 68];

    const int tid  = threadIdx.x;
    const int lane = tid & 31;
    const int warp = tid >> 5;
    const int wm   = warp >> 2;   // 0..1
    const int wn   = warp & 3;    // 0..3
    const int b    = blockIdx.y;
    const int nt   = blockIdx.x;
    const int c    = cat_ids[b];

    const float* A = Abase + (size_t)b * 64 * K;
    const float* W = Wbase + (size_t)c * wcat_stride + nt * NT;

    const uint32_t sAh = smem_u32(As_hi), sAl = smem_u32(As_lo);
    const uint32_t sBh = smem_u32(Bs_hi), sBl = smem_u32(Bs_lo);

    float acc[2][4][4];
    #pragma unroll
    for (int i = 0; i < 2; ++i)
        #pragma unroll
        for (int j = 0; j < 4; ++j)
            #pragma unroll
            for (int q = 0; q < 4; ++q) acc[i][j][q] = 0.0f;

    constexpr int NCHUNK = K / KC;

    // Load mappings:
    // A: item i = tid + 256*r : kq = i&7 (float4 along k), m = i>>3
    // B: item i = tid + 256*r : nq = i&31 (float4 along n), kp = i>>5 (k-pair row)
    float4 pa[2], pb0[2], pb1[2];
    {
        #pragma unroll
        for (int r = 0; r < 2; ++r) {
            int i = tid + r * 256, kq = i & 7, m = i >> 3;
            pa[r] = *(const float4*)&A[(size_t)m * K + kq * 4];
        }
        #pragma unroll
        for (int r = 0; r < 2; ++r) {
            int i = tid + r * 256, nq = i & 31, kp = i >> 5;
            pb0[r] = *(const float4*)&W[(size_t)(kp * 2)     * HH + nq * 4];
            pb1[r] = *(const float4*)&W[(size_t)(kp * 2 + 1) * HH + nq * 4];
        }
    }

    // ldmatrix lane addressing (constant across chunks)
    const int l15 = lane & 15;
    const int g16 = lane >> 4;

    for (int ch = 0; ch < NCHUNK; ++ch) {
        __syncthreads();

        // ---- STS: A as bf16 [m][k], stride 20 words ----
        #pragma unroll
        for (int r = 0; r < 2; ++r) {
            int i = tid + r * 256, kq = i & 7, m = i >> 3;
            float4 v = pa[r];
            uint32_t h0, l0, h1, l1;
            split_pair(v.x, v.y, h0, l0);
            split_pair(v.z, v.w, h1, l1);
            int idx = m * 20 + kq * 2;
            *(uint2*)&As_hi[idx] = make_uint2(h0, h1);
            *(uint2*)&As_lo[idx] = make_uint2(l0, l1);
        }
        // ---- STS: B as bf16 [k][n], stride 68 words ----
        #pragma unroll
        for (int r = 0; r < 2; ++r) {
            int i = tid + r * 256, nq = i & 31, kp = i >> 5;
            float4 v0 = pb0[r], v1 = pb1[r];
            uint32_t h01, l01, h23, l23;
            split_pair(v0.x, v0.y, h01, l01);
            split_pair(v0.z, v0.w, h23, l23);
            int idx0 = (kp * 2) * 68 + nq * 2;
            *(uint2*)&Bs_hi[idx0] = make_uint2(h01, h23);
            *(uint2*)&Bs_lo[idx0] = make_uint2(l01, l23);
            split_pair(v1.x, v1.y, h01, l01);
            split_pair(v1.z, v1.w, h23, l23);
            int idx1 = (kp * 2 + 1) * 68 + nq * 2;
            *(uint2*)&Bs_hi[idx1] = make_uint2(h01, h23);
            *(uint2*)&Bs_lo[idx1] = make_uint2(l01, l23);
        }
        __syncthreads();

        // ---- prefetch next chunk (overlaps MMA below) ----
        if (ch + 1 < NCHUNK) {
            int k0 = (ch + 1) * KC;
            #pragma unroll
            for (int r = 0; r < 2; ++r) {
                int i = tid + r * 256, kq = i & 7, m = i >> 3;
                pa[r] = *(const float4*)&A[(size_t)m * K + k0 + kq * 4];
            }
            #pragma unroll
            for (int r = 0; r < 2; ++r) {
                int i = tid + r * 256, nq = i & 31, kp = i >> 5;
                pb0[r] = *(const float4*)&W[(size_t)(k0 + kp * 2)     * HH + nq * 4];
                pb1[r] = *(const float4*)&W[(size_t)(k0 + kp * 2 + 1) * HH + nq * 4];
            }
        }

        // ---- MMA phase: two k16 steps, ldmatrix frags ----
        #pragma unroll
        for (int t = 0; t < 2; ++t) {
            uint32_t Ah[2][4], Al[2][4];
            #pragma unroll
            for (int ms = 0; ms < 2; ++ms) {
                int r0 = wm * 32 + ms * 16 + l15;
                uint32_t abyte = r0 * 80 + t * 32 + g16 * 16;
                ldsm_x4(Ah[ms], sAh + abyte);
                ldsm_x4(Al[ms], sAl + abyte);
            }
            uint32_t Bh[2][4], Bl[2][4];
            #pragma unroll
            for (int nfp = 0; nfp < 2; ++nfp) {
                int kr = t * 16 + l15;
                uint32_t bbyte = kr * 272 + (wn * 32 + nfp * 16 + g16 * 8) * 2;
                ldsm_x4_t(Bh[nfp], sBh + bbyte);
                ldsm_x4_t(Bl[nfp], sBl + bbyte);
            }
            #pragma unroll
            for (int nf = 0; nf < 4; ++nf) {
                uint32_t bh0 = Bh[nf >> 1][(nf & 1) * 2];
                uint32_t bh1 = Bh[nf >> 1][(nf & 1) * 2 + 1];
                uint32_t bl0 = Bl[nf >> 1][(nf & 1) * 2];
                uint32_t bl1 = Bl[nf >> 1][(nf & 1) * 2 + 1];
                #pragma unroll
                for (int ms = 0; ms < 2; ++ms) {
                    mma_bf16(acc[ms][nf], Ah[ms], bh0, bh1);   // hi*hi
                    mma_bf16(acc[ms][nf], Ah[ms], bl0, bl1);   // hi*lo
                    mma_bf16(acc[ms][nf], Al[ms], bh0, bh1);   // lo*hi
                }
            }
        }
    }

    // ---- epilogue ----
    const float* addp = (ADDMODE == 0) ? (addv + (size_t)c * HH)
                                       : (addv + (size_t)b * HH);
    const int lr = lane >> 2;
    const int lc = lane & 3;
    #pragma unroll
    for (int ms = 0; ms < 2; ++ms) {
        int r0 = wm * 32 + ms * 16 + lr;
        #pragma unroll
        for (int nf = 0; nf < 4; ++nf) {
            int ncol = nt * NT + wn * 32 + nf * 8 + lc * 2;
            float bv0 = addp[ncol], bv1 = addp[ncol + 1];
            float v0 = acc[ms][nf][0] + bv0;
            float v1 = acc[ms][nf][1] + bv1;
            float v2 = acc[ms][nf][2] + bv0;
            float v3 = acc[ms][nf][3] + bv1;
            if (ACT == 1) {
                v0 = v0 / (1.0f + expf(-v0));
                v1 = v1 / (1.0f + expf(-v1));
                v2 = v2 / (1.0f + expf(-v2));
                v3 = v3 / (1.0f + expf(-v3));
            }
            *(float2*)&out[((size_t)b * TT + r0)     * HH + ncol] = make_float2(v0, v1);
            *(float2*)&out[((size_t)b * TT + r0 + 8) * HH + ncol] = make_float2(v2, v3);
        }
    }
}

extern "C" void kernel_launch(void* const* d_in, const int* in_sizes, int n_in,
                              void* d_out, int out_size) {
    const float* actions   = (const float*)d_in[0];
    const int*   timesteps = (const int*)d_in[1];
    const int*   cat_ids   = (const int*)d_in[2];
    const float* W1 = (const float*)d_in[3];
    const float* b1 = (const float*)d_in[4];
    const float* W2 = (const float*)d_in[5];
    const float* b2 = (const float*)d_in[6];
    const float* W3 = (const float*)d_in[7];
    const float* b3 = (const float*)d_in[8];
    float* out = (float*)d_out;

    float* aemb, * hbuf, * tauc;
    cudaGetSymbolAddress((void**)&aemb, g_aemb);
    cudaGetSymbolAddress((void**)&hbuf, g_h);
    cudaGetSymbolAddress((void**)&tauc, g_tauc);

    prep_kernel<<<1, CC>>>(cat_ids);
    tau1_kernel<<<BB, 256>>>(timesteps);

    // layer 1 (small GEMM)
    mma_layer<AA, 0, 0><<<dim3(HH / NT, BB), 256>>>(
        actions, W1, (size_t)AA * HH, b1, cat_ids, aemb);

    // tau matvec: K-split partials + deterministic reduce
    tau2_kernel<<<dim3(HH / 2 / 128, CC, KSPLIT), 128>>>(W2);
    tau3_kernel<<<dim3(HH / 256, BB), 256>>>(cat_ids, b2);

    // layer 2: h = swish(a_emb @ W2[:1024] + tauc)
    mma_layer<HH, 1, 1><<<dim3(HH / NT, BB), 256>>>(
        aemb, W2, (size_t)2 * HH * HH, tauc, cat_ids, hbuf);

    // layer 3
    mma_layer<HH, 0, 0><<<dim3(HH / NT, BB), 256>>>(
        hbuf, W3, (size_t)HH * HH, b3, cat_ids, out);
}